// round 1
// baseline (speedup 1.0000x reference)
#include <cuda_runtime.h>

// Problem: ConvTranspose3d(32->64,k=3,s=2,p=1)+bias, *0.5, MaxPool3d(2), mean, clamp.
// Restructured as k=2 valid conv on 32^3 input over pool-window grid p in [0,31)^3.
// Window (p) output e=(ed,eh,ew) in {0,1}^3:
//   taps per dim: d=0 -> k=e+1 ; d=1 (only if e==1) -> k=0
// Epilogue: max over 8 e's, sum over windows, then 0.5*(S/31^3 + bias), clamp [0,1].

#define CIN   32
#define COUT  64
#define DIM   32
#define NPD   31          // pd blocks per b
#define NBLK_PER_B 62     // 31 pd * 2 h-tiles
#define XS_FLOATS (CIN*2*17*32)      // 34816
#define WS_FLOATS (CIN*28)           // 896 (27 taps padded to 28)
#define WSUM_FLOATS (8*64)           // 512
#define SMEM_FLOATS (XS_FLOATS + WS_FLOATS + WSUM_FLOATS)
#define SMEM_BYTES (SMEM_FLOATS * 4) // 144896

__device__ float g_partials[16 * NBLK_PER_B * 64];

__global__ __launch_bounds__(256, 1)
void conv_main_kernel(const float* __restrict__ x, const float* __restrict__ w)
{
    extern __shared__ float sm[];
    float* xs   = sm;                       // [cin][2][17][32]
    float* ws   = sm + XS_FLOATS;           // [cin][28]
    float* wsum = sm + XS_FLOATS + WS_FLOATS; // [8 warps][64 cout]

    const int b   = blockIdx.y;
    const int pd  = blockIdx.x >> 1;
    const int ht  = blockIdx.x & 1;
    const int ph0 = ht ? 16 : 0;
    const int nh  = ht ? 15 : 16;           // pool-window rows handled in this tile
    const int nrows = nh + 1;               // x rows needed (halo +1)
    const int tid = threadIdx.x;

    // ---- load x slab: x[b, :, pd..pd+1, ph0..ph0+nrows-1, :] (float4, coalesced) ----
    {
        const int total4 = CIN * 2 * nrows * 8;   // 8 float4 per 32-float row
        for (int i = tid; i < total4; i += 256) {
            int w4 = i & 7;
            int r  = i >> 3;
            int h  = r % nrows; r /= nrows;
            int d  = r & 1;
            int cin = r >> 1;
            const float4* src = reinterpret_cast<const float4*>(
                x + ((((b*CIN + cin)*DIM + (pd + d))*DIM + (ph0 + h))*DIM)) + w4;
            reinterpret_cast<float4*>(xs + ((cin*2 + d)*17 + h)*32)[w4] = *src;
        }
    }

    const int lane = tid & 31;
    const int wid  = tid >> 5;       // 0..7
    const int pw   = lane;           // window col, active if < 31
    const bool act1 = (pw < 31);                 // window (ph0+wid, pw)
    const bool act2 = act1 && ((wid + 8) < nh);  // window (ph0+wid+8, pw)

    for (int cout = 0; cout < COUT; ++cout) {
        __syncthreads();  // protects ws reuse (and first iter: xs visibility)
        // stage weights for this cout: w[cin][cout][27] -> ws[cin][0..26]
        for (int i = tid; i < CIN*27; i += 256) {
            int cin = i / 27, k = i - cin*27;
            ws[cin*28 + k] = w[(cin*COUT + cout)*27 + k];
        }
        __syncthreads();

        float acc1[8], acc2[8];
        #pragma unroll
        for (int e = 0; e < 8; ++e) { acc1[e] = 0.f; acc2[e] = 0.f; }

        #pragma unroll 2
        for (int cin = 0; cin < CIN; ++cin) {
            // weights to registers (broadcast LDS.128)
            float wr[28];
            const float4* wv = reinterpret_cast<const float4*>(ws + cin*28);
            #pragma unroll
            for (int i = 0; i < 7; ++i)
                *reinterpret_cast<float4*>(&wr[i*4]) = wv[i];

            // x patch for both windows
            const float* xb = xs + cin*1088;   // 2*17*32
            float xv1[8], xv2[8];
            #pragma unroll
            for (int dd = 0; dd < 2; ++dd)
            #pragma unroll
            for (int dh = 0; dh < 2; ++dh)
            #pragma unroll
            for (int dw = 0; dw < 2; ++dw) {
                int o = dd*544 + dh*32 + dw;
                xv1[dd*4 + dh*2 + dw] = xb[o + (wid    )*32 + pw];
                xv2[dd*4 + dh*2 + dw] = xb[o + (wid + 8)*32 + pw];
            }

            // 27 taps per window
            #pragma unroll
            for (int ed = 0; ed < 2; ++ed)
            #pragma unroll
            for (int eh = 0; eh < 2; ++eh)
            #pragma unroll
            for (int ew = 0; ew < 2; ++ew) {
                const int eidx = ed*4 + eh*2 + ew;
                #pragma unroll
                for (int dd = 0; dd <= ed; ++dd)
                #pragma unroll
                for (int dh = 0; dh <= eh; ++dh)
                #pragma unroll
                for (int dw = 0; dw <= ew; ++dw) {
                    const int kd = dd ? 0 : ed + 1;
                    const int kh = dh ? 0 : eh + 1;
                    const int kw = dw ? 0 : ew + 1;
                    const float wt = wr[(kd*3 + kh)*3 + kw];
                    const int didx = dd*4 + dh*2 + dw;
                    acc1[eidx] = fmaf(xv1[didx], wt, acc1[eidx]);
                    acc2[eidx] = fmaf(xv2[didx], wt, acc2[eidx]);
                }
            }
        }

        // max over the 8 pool-window candidates, then sum across block
        float m1 = fmaxf(fmaxf(fmaxf(acc1[0], acc1[1]), fmaxf(acc1[2], acc1[3])),
                         fmaxf(fmaxf(acc1[4], acc1[5]), fmaxf(acc1[6], acc1[7])));
        float m2 = fmaxf(fmaxf(fmaxf(acc2[0], acc2[1]), fmaxf(acc2[2], acc2[3])),
                         fmaxf(fmaxf(acc2[4], acc2[5]), fmaxf(acc2[6], acc2[7])));
        float v = (act1 ? m1 : 0.f) + (act2 ? m2 : 0.f);
        #pragma unroll
        for (int o = 16; o > 0; o >>= 1)
            v += __shfl_down_sync(0xFFFFFFFFu, v, o);
        if (lane == 0) wsum[wid*64 + cout] = v;
    }

    __syncthreads();
    if (tid < 64) {
        float s = 0.f;
        #pragma unroll
        for (int i = 0; i < 8; ++i) s += wsum[i*64 + tid];
        g_partials[(b*NBLK_PER_B + blockIdx.x)*64 + tid] = s;
    }
}

__global__ void finalize_kernel(const float* __restrict__ bias, float* __restrict__ out)
{
    const int t = threadIdx.x;          // 1024 threads = 16*64
    if (t >= 16*64) return;
    const int b = t >> 6, c = t & 63;
    float s = 0.f;
    #pragma unroll 8
    for (int i = 0; i < NBLK_PER_B; ++i)
        s += g_partials[(b*NBLK_PER_B + i)*64 + c];
    float v = 0.5f * (s * (1.0f / 29791.0f) + bias[c]);
    out[t] = fminf(fmaxf(v, 0.f), 1.f);
}

extern "C" void kernel_launch(void* const* d_in, const int* in_sizes, int n_in,
                              void* d_out, int out_size)
{
    const float* x    = (const float*)d_in[0];
    const float* w    = (const float*)d_in[1];
    const float* bias = (const float*)d_in[2];
    float* out = (float*)d_out;

    cudaFuncSetAttribute(conv_main_kernel,
                         cudaFuncAttributeMaxDynamicSharedMemorySize, SMEM_BYTES);

    dim3 grid(NBLK_PER_B, 16);
    conv_main_kernel<<<grid, 256, SMEM_BYTES>>>(x, w);
    finalize_kernel<<<1, 1024>>>(bias, out);
}

// round 3
// speedup vs baseline: 9.8467x; 9.8467x over previous
#include <cuda_runtime.h>
#include <cuda_bf16.h>
#include <cstdint>

#define DIM 32
#define CIN 32
#define COUT 64
#define TILES_PER_B 248         // 31 pd * 8 ph-tiles (4 window-rows each)

// ---- smem layout ----
#define SM_MBAR   0
#define SM_XS     1024                  // bf16 [cin][2][5][32] = 20480 (+slack)
#define SM_AT     22528                 // At[k=256][256B] = 65536
#define SM_B      88064                 // 27 * 4096 = 110592
#define SM_WSUM   198656                // 8 warps * 32 floats = 1024
#define SMEM_TOTAL 199680

__device__ __align__(256) __nv_bfloat16 g_wb[27 * 32 * 64];   // pre-swizzled taps
__device__ float g_partials[16 * TILES_PER_B * 64];

// ------------------------- helpers -------------------------
__device__ __forceinline__ uint32_t smem_u32(const void* p) {
    uint32_t a;
    asm("{ .reg .u64 t; cvta.to.shared.u64 t, %1; cvt.u32.u64 %0, t; }" : "=r"(a) : "l"(p));
    return a;
}
#define MBAR_INIT(addr, cnt) \
    asm volatile("mbarrier.init.shared.b64 [%0], %1;" :: "r"(addr), "r"(cnt) : "memory")
#define MBAR_EXPECT_TX(addr, bytes) \
    asm volatile("mbarrier.arrive.expect_tx.shared.b64 _, [%0], %1;" :: "r"(addr), "r"(bytes) : "memory")
#define MBAR_WAIT(addr, parity) do { \
    uint32_t _m = (addr); uint32_t _p = (parity); uint32_t _d; \
    asm volatile("{\n\t.reg .pred p;\n\t" \
        "mbarrier.try_wait.parity.acquire.cta.shared::cta.b64 p, [%1], %2;\n\t" \
        "selp.b32 %0, 1, 0, p;\n\t}" : "=r"(_d) : "r"(_m), "r"(_p) : "memory"); \
    if (!_d) { \
        asm volatile("{\n\t.reg .pred P1;\n\t" \
            "WL_%=:\n\t" \
            "mbarrier.try_wait.parity.acquire.cta.shared::cta.b64 P1, [%0], %1, 0x989680;\n\t" \
            "@P1 bra.uni WD_%=;\n\tbra.uni WL_%=;\n\tWD_%=:\n\t}" \
            :: "r"(_m), "r"(_p) : "memory"); \
    } } while (0)
#define FENCE_ASYNC() asm volatile("fence.proxy.async.shared::cta;" ::: "memory")
#define BULK_G2S(dst, src, bytes, mbar) \
    asm volatile("cp.async.bulk.shared::cta.global.mbarrier::complete_tx::bytes [%0], [%1], %2, [%3];" \
                 :: "r"(dst), "l"(src), "r"(bytes), "r"(mbar) : "memory")

__device__ __forceinline__ void ldsm_x4t(uint32_t (&r)[4], uint32_t a) {
    asm volatile("ldmatrix.sync.aligned.m8n8.x4.trans.shared.b16 {%0,%1,%2,%3}, [%4];"
                 : "=r"(r[0]), "=r"(r[1]), "=r"(r[2]), "=r"(r[3]) : "r"(a));
}
__device__ __forceinline__ void mma16816(float (&d)[4], const uint32_t (&a)[4],
                                         uint32_t b0, uint32_t b1) {
    asm volatile("mma.sync.aligned.m16n8k16.row.col.f32.bf16.bf16.f32 "
                 "{%0,%1,%2,%3},{%4,%5,%6,%7},{%8,%9},{%0,%1,%2,%3};"
                 : "+f"(d[0]), "+f"(d[1]), "+f"(d[2]), "+f"(d[3])
                 : "r"(a[0]), "r"(a[1]), "r"(a[2]), "r"(a[3]), "r"(b0), "r"(b1));
}

// ------------------- weight expansion: g_wb[t][cin][cout], SW128 per tap block ----
__global__ void init_wb(const float* __restrict__ w) {
    int idx = blockIdx.x * 256 + threadIdx.x;      // < 55296
    if (idx >= 27 * 32 * 64) return;
    int cout = idx & 63;
    int cin  = (idx >> 6) & 31;
    int t    = idx >> 11;
    float val = w[(cin * COUT + cout) * 27 + t];
    uint32_t off = (uint32_t)cin * 128u + (uint32_t)cout * 2u;
    uint32_t sw  = off ^ (((off >> 7) & 7) << 4);
    *(__nv_bfloat16*)((char*)g_wb + (size_t)t * 4096 + sw) = __float2bfloat16(val);
}

// ------------------------------ main ------------------------------
__global__ __launch_bounds__(256, 1)
void conv_mma_kernel(const float* __restrict__ x)
{
    extern __shared__ char sm[];
    const uint32_t smb = smem_u32(sm);
    const int tid = threadIdx.x, wid = tid >> 5, lid = tid & 31;
    const int b   = blockIdx.y;
    const int pd  = blockIdx.x >> 3;
    const int ph0 = (blockIdx.x & 7) * 4;
    const int nh  = min(4, 31 - ph0);

    // mbarrier init (visible to all via the syncthreads below)
    if (tid == 0) { MBAR_INIT(smb + SM_MBAR, 1); }

    // ---- stage x slab -> bf16 xs[cin][2][5][32] (64B rows), coalesced ----
    for (int i = tid; i < 2560; i += 256) {
        int w4 = i & 7, r = i >> 3;
        int h = r % 5, r2 = r / 5;
        int dd = r2 & 1, cin = r2 >> 1;
        int hg = ph0 + h;
        float4 f = make_float4(0.f, 0.f, 0.f, 0.f);
        if (hg < 32)
            f = *(const float4*)(x + (size_t)((((b * CIN + cin) * DIM + (pd + dd)) * DIM + hg) * DIM) + w4 * 4);
        __nv_bfloat162 p0 = __floats2bfloat162_rn(f.x, f.y);
        __nv_bfloat162 p1 = __floats2bfloat162_rn(f.z, f.w);
        *(uint2*)(sm + SM_XS + ((cin * 2 + dd) * 5 + h) * 64 + w4 * 8) =
            make_uint2(*(uint32_t*)&p0, *(uint32_t*)&p1);
    }
    __syncthreads();

    // kick off B streaming (overlaps At build)
    if (tid == 0) {
        FENCE_ASYNC();
        MBAR_EXPECT_TX(smb + SM_MBAR, 110592u);
        BULK_G2S(smb + SM_B, (const char*)g_wb, 110592u, smb + SM_MBAR);
    }

    // ---- build At[k=(pos,cin)][m=(phl,pw)] : 256 rows x 256B, swizzled ----
    for (int it = 0; it < 16; ++it) {
        int idx = it * 256 + tid;                   // 4096 16B-chunks
        int q = idx & 15, krow = idx >> 4;
        int pos = krow >> 5, cin = krow & 31;
        int dd = pos >> 2, dh = (pos >> 1) & 1, dw = pos & 1;
        int phl = q >> 2, pw0 = (q & 3) * 8;
        const char* srow = sm + SM_XS + ((cin * 2 + dd) * 5 + (phl + dh)) * 64;
        uint4 v;
        if (dw == 0) {
            v = *(const uint4*)(srow + pw0 * 2);
        } else {
            uint4 a = *(const uint4*)(srow + pw0 * 2);
            uint32_t bb = *(const uint32_t*)(srow + pw0 * 2 + 16);
            v.x = __funnelshift_r(a.x, a.y, 16);
            v.y = __funnelshift_r(a.y, a.z, 16);
            v.z = __funnelshift_r(a.z, a.w, 16);
            v.w = __funnelshift_r(a.w, bb, 16);
        }
        if (phl >= nh) v = make_uint4(0u, 0u, 0u, 0u);
        if (pw0 == 24) v.w &= 0x0000FFFFu;          // col pw=31 invalid
        uint32_t off = (uint32_t)krow * 256u + (((uint32_t)q * 16u) ^ (((uint32_t)krow & 7u) << 4));
        *(uint4*)(sm + SM_AT + off) = v;
    }
    __syncthreads();
    MBAR_WAIT(smb + SM_MBAR, 0);     // B resident

    // ---- per-warp tile: m32 (windows) x n32 (couts) ----
    const int mt = wid >> 1, nt = wid & 1;
    const int m0 = mt * 32, n0 = nt * 32;
    const uint32_t xm = (uint32_t)(lid & 7) << 4;
    const int krA = ((lid >> 4) & 1) * 8 + (lid & 7);
    const int mc0 = m0 + ((lid >> 3) & 1) * 8;
    const uint32_t adrA0 = smb + SM_AT + krA * 256 + (((uint32_t)(mc0      ) * 2u) ^ xm);
    const uint32_t adrA1 = smb + SM_AT + krA * 256 + (((uint32_t)(mc0 + 16 ) * 2u) ^ xm);
    const int krB = ((lid >> 3) & 1) * 8 + (lid & 7);
    const int nc0 = n0 + ((lid >> 4) & 1) * 8;
    const uint32_t adrB0 = smb + SM_B + krB * 128 + (((uint32_t)(nc0      ) * 2u) ^ xm);
    const uint32_t adrB1 = smb + SM_B + krB * 128 + (((uint32_t)(nc0 + 16 ) * 2u) ^ xm);

    float vmax[2][4][4];
    #pragma unroll
    for (int i = 0; i < 2; ++i)
    #pragma unroll
    for (int j = 0; j < 4; ++j)
    #pragma unroll
    for (int k = 0; k < 4; ++k) vmax[i][j][k] = -3.4e38f;

    #pragma unroll
    for (int e = 0; e < 8; ++e) {
        float acc[2][4][4];
        #pragma unroll
        for (int i = 0; i < 2; ++i)
        #pragma unroll
        for (int j = 0; j < 4; ++j)
        #pragma unroll
        for (int k = 0; k < 4; ++k) acc[i][j][k] = 0.f;

        #pragma unroll
        for (int pos = 0; pos < 8; ++pos) {
            if (pos & ~e & 7) continue;             // d must satisfy d <= e bitwise
            const int kd = (pos & 4) ? 0 : (((e >> 2) & 1) + 1);
            const int kh = (pos & 2) ? 0 : (((e >> 1) & 1) + 1);
            const int kw = (pos & 1) ? 0 : ((e & 1) + 1);
            const int t  = (kd * 3 + kh) * 3 + kw;
            #pragma unroll
            for (int kb2 = 0; kb2 < 2; ++kb2) {
                const int kb = pos * 2 + kb2;
                uint32_t A0[4], A1[4], B0[4], B1[4];
                ldsm_x4t(A0, adrA0 + kb * 4096);
                ldsm_x4t(A1, adrA1 + kb * 4096);
                ldsm_x4t(B0, adrB0 + t * 4096 + kb2 * 2048);
                ldsm_x4t(B1, adrB1 + t * 4096 + kb2 * 2048);
                mma16816(acc[0][0], A0, B0[0], B0[1]);
                mma16816(acc[0][1], A0, B0[2], B0[3]);
                mma16816(acc[0][2], A0, B1[0], B1[1]);
                mma16816(acc[0][3], A0, B1[2], B1[3]);
                mma16816(acc[1][0], A1, B0[0], B0[1]);
                mma16816(acc[1][1], A1, B0[2], B0[3]);
                mma16816(acc[1][2], A1, B1[0], B1[1]);
                mma16816(acc[1][3], A1, B1[2], B1[3]);
            }
        }
        #pragma unroll
        for (int i = 0; i < 2; ++i)
        #pragma unroll
        for (int j = 0; j < 4; ++j)
        #pragma unroll
        for (int k = 0; k < 4; ++k) vmax[i][j][k] = fmaxf(vmax[i][j][k], acc[i][j][k]);
    }

    // ---- epilogue: sum vmax over windows (rows), reduce to per-cout ----
    float* wsumf = (float*)(sm + SM_WSUM);
    #pragma unroll
    for (int nf = 0; nf < 4; ++nf) {
        float s0 = vmax[0][nf][0] + vmax[0][nf][2] + vmax[1][nf][0] + vmax[1][nf][2];
        float s1 = vmax[0][nf][1] + vmax[0][nf][3] + vmax[1][nf][1] + vmax[1][nf][3];
        #pragma unroll
        for (int off = 4; off < 32; off <<= 1) {
            s0 += __shfl_xor_sync(0xFFFFFFFFu, s0, off);
            s1 += __shfl_xor_sync(0xFFFFFFFFu, s1, off);
        }
        if (lid < 4) {
            wsumf[wid * 32 + nf * 8 + lid * 2]     = s0;
            wsumf[wid * 32 + nf * 8 + lid * 2 + 1] = s1;
        }
    }
    __syncthreads();

    if (tid < 64) {
        int ntc = tid >> 5, cl = tid & 31;
        float s = wsumf[(0 * 2 + ntc) * 32 + cl] + wsumf[(1 * 2 + ntc) * 32 + cl]
                + wsumf[(2 * 2 + ntc) * 32 + cl] + wsumf[(3 * 2 + ntc) * 32 + cl];
        g_partials[(b * TILES_PER_B + blockIdx.x) * 64 + tid] = s;
    }
}

__global__ void finalize_kernel(const float* __restrict__ bias, float* __restrict__ out)
{
    int bb = blockIdx.x;
    int t = threadIdx.x;                 // 256
    int cout = t >> 2, q = t & 3;
    float s = 0.f;
    for (int i = q; i < TILES_PER_B; i += 4)
        s += g_partials[(bb * TILES_PER_B + i) * 64 + cout];
    s += __shfl_down_sync(0xFFFFFFFFu, s, 2, 4);
    s += __shfl_down_sync(0xFFFFFFFFu, s, 1, 4);
    if (q == 0) {
        float v = 0.5f * (s * (1.0f / 29791.0f) + bias[cout]);
        out[bb * 64 + cout] = fminf(fmaxf(v, 0.f), 1.f);
    }
}

extern "C" void kernel_launch(void* const* d_in, const int* in_sizes, int n_in,
                              void* d_out, int out_size)
{
    const float* x    = (const float*)d_in[0];
    const float* w    = (const float*)d_in[1];
    const float* bias = (const float*)d_in[2];
    float* out = (float*)d_out;

    cudaFuncSetAttribute(conv_mma_kernel,
                         cudaFuncAttributeMaxDynamicSharedMemorySize, SMEM_TOTAL);

    init_wb<<<216, 256>>>(w);
    dim3 grid(TILES_PER_B, 16);
    conv_mma_kernel<<<grid, 256, SMEM_TOTAL>>>(x);
    finalize_kernel<<<16, 256>>>(bias, out);
}

// round 4
// speedup vs baseline: 11.9042x; 1.2090x over previous
#include <cuda_runtime.h>
#include <cuda_bf16.h>
#include <cstdint>

#define DIM 32
#define CIN 32
#define COUT 64
#define TILES_PER_B 248
#define NTILES (16 * TILES_PER_B)      // 3968
#define NBLOCKS 148

// ---- smem layout (offsets multiples of 1024 where swizzle matters) ----
#define SM_MBAR   0
#define SM_XS     1024                  // bf16 [cin][2][5][32] = 20480
#define SM_AT     22528                 // At[k=256][256B] = 65536
#define SM_B      88064                 // 27 * 4096 = 110592
#define SM_WSUM   198656                // 8 warps * 32 floats = 1024
#define SMEM_TOTAL 199680

__device__ __align__(256) __nv_bfloat16 g_wb[27 * 32 * 64];
__device__ float g_partials[NTILES * 64];

// ------------------------- helpers -------------------------
__device__ __forceinline__ uint32_t smem_u32(const void* p) {
    uint32_t a;
    asm("{ .reg .u64 t; cvta.to.shared.u64 t, %1; cvt.u32.u64 %0, t; }" : "=r"(a) : "l"(p));
    return a;
}
#define MBAR_INIT(addr, cnt) \
    asm volatile("mbarrier.init.shared.b64 [%0], %1;" :: "r"(addr), "r"(cnt) : "memory")
#define MBAR_EXPECT_TX(addr, bytes) \
    asm volatile("mbarrier.arrive.expect_tx.shared.b64 _, [%0], %1;" :: "r"(addr), "r"(bytes) : "memory")
#define MBAR_WAIT(addr, parity) do { \
    uint32_t _m = (addr); uint32_t _p = (parity); uint32_t _d; \
    asm volatile("{\n\t.reg .pred p;\n\t" \
        "mbarrier.try_wait.parity.acquire.cta.shared::cta.b64 p, [%1], %2;\n\t" \
        "selp.b32 %0, 1, 0, p;\n\t}" : "=r"(_d) : "r"(_m), "r"(_p) : "memory"); \
    if (!_d) { \
        asm volatile("{\n\t.reg .pred P1;\n\t" \
            "WL_%=:\n\t" \
            "mbarrier.try_wait.parity.acquire.cta.shared::cta.b64 P1, [%0], %1, 0x989680;\n\t" \
            "@P1 bra.uni WD_%=;\n\tbra.uni WL_%=;\n\tWD_%=:\n\t}" \
            :: "r"(_m), "r"(_p) : "memory"); \
    } } while (0)
#define FENCE_ASYNC() asm volatile("fence.proxy.async.shared::cta;" ::: "memory")
#define BULK_G2S(dst, src, bytes, mbar) \
    asm volatile("cp.async.bulk.shared::cta.global.mbarrier::complete_tx::bytes [%0], [%1], %2, [%3];" \
                 :: "r"(dst), "l"(src), "r"(bytes), "r"(mbar) : "memory")

__device__ __forceinline__ void ldsm_x4t(uint32_t (&r)[4], uint32_t a) {
    asm volatile("ldmatrix.sync.aligned.m8n8.x4.trans.shared.b16 {%0,%1,%2,%3}, [%4];"
                 : "=r"(r[0]), "=r"(r[1]), "=r"(r[2]), "=r"(r[3]) : "r"(a));
}
__device__ __forceinline__ void mma16816(float (&d)[4], const uint32_t (&a)[4],
                                         uint32_t b0, uint32_t b1) {
    asm volatile("mma.sync.aligned.m16n8k16.row.col.f32.bf16.bf16.f32 "
                 "{%0,%1,%2,%3},{%4,%5,%6,%7},{%8,%9},{%0,%1,%2,%3};"
                 : "+f"(d[0]), "+f"(d[1]), "+f"(d[2]), "+f"(d[3])
                 : "r"(a[0]), "r"(a[1]), "r"(a[2]), "r"(a[3]), "r"(b0), "r"(b1));
}

// x slab prefetch: 10 float4 per thread (2560 total = cin32 * d2 * h5 * 8)
__device__ __forceinline__ void ldg_slab(const float* __restrict__ x,
                                         int b, int pd, int ph0, int tid,
                                         float4 (&xr)[10]) {
    #pragma unroll
    for (int j = 0; j < 10; ++j) {
        int i = j * 256 + tid;
        int w4 = i & 7, r = i >> 3;
        int h = r % 5, r2 = r / 5;
        int dd = r2 & 1, cin = r2 >> 1;
        int hg = ph0 + h;
        float4 f = make_float4(0.f, 0.f, 0.f, 0.f);
        if (hg < 32)
            f = *(const float4*)(x + (size_t)((((b * CIN + cin) * DIM + (pd + dd)) * DIM + hg) * DIM) + w4 * 4);
        xr[j] = f;
    }
}
__device__ __forceinline__ void sts_slab(char* sm, int tid, const float4 (&xr)[10]) {
    #pragma unroll
    for (int j = 0; j < 10; ++j) {
        int i = j * 256 + tid;
        int w4 = i & 7, r = i >> 3;
        int h = r % 5, r2 = r / 5;
        int dd = r2 & 1, cin = r2 >> 1;
        __nv_bfloat162 p0 = __floats2bfloat162_rn(xr[j].x, xr[j].y);
        __nv_bfloat162 p1 = __floats2bfloat162_rn(xr[j].z, xr[j].w);
        *(uint2*)(sm + SM_XS + ((cin * 2 + dd) * 5 + h) * 64 + w4 * 8) =
            make_uint2(*(uint32_t*)&p0, *(uint32_t*)&p1);
    }
}

// ------------------- weight expansion: g_wb[t][cin][cout], SW128 per tap ----
__global__ void init_wb(const float* __restrict__ w) {
    int idx = blockIdx.x * 256 + threadIdx.x;
    if (idx >= 27 * 32 * 64) return;
    int cout = idx & 63;
    int cin  = (idx >> 6) & 31;
    int t    = idx >> 11;
    float val = w[(cin * COUT + cout) * 27 + t];
    uint32_t off = (uint32_t)cin * 128u + (uint32_t)cout * 2u;
    uint32_t sw  = off ^ (((off >> 7) & 7) << 4);
    *(__nv_bfloat16*)((char*)g_wb + (size_t)t * 4096 + sw) = __float2bfloat16(val);
}

// ------------------------------ main (persistent) ------------------------------
__global__ __launch_bounds__(256, 1)
void conv_mma_kernel(const float* __restrict__ x)
{
    extern __shared__ char sm[];
    const uint32_t smb = smem_u32(sm);
    const int tid = threadIdx.x, wid = tid >> 5, lid = tid & 31;
    const int bid = blockIdx.x;

    // B resident: one bulk copy per CTA
    if (tid == 0) {
        MBAR_INIT(smb + SM_MBAR, 1);
        FENCE_ASYNC();
        MBAR_EXPECT_TX(smb + SM_MBAR, 110592u);
        BULK_G2S(smb + SM_B, (const char*)g_wb, 110592u, smb + SM_MBAR);
    }

    // prologue: stage x for first tile
    float4 xr[10];
    {
        int t0 = bid;
        int b0 = t0 / TILES_PER_B, r0 = t0 % TILES_PER_B;
        ldg_slab(x, b0, r0 >> 3, (r0 & 7) * 4, tid, xr);
        sts_slab(sm, tid, xr);
    }
    __syncthreads();                 // xs ready; mbar init visible
    MBAR_WAIT(smb + SM_MBAR, 0);     // B resident

    // mainloop invariant addresses
    const int mt = wid >> 1, nt = wid & 1;
    const int m0 = mt * 32, n0 = nt * 32;
    const uint32_t xm = (uint32_t)(lid & 7) << 4;
    const int krA = ((lid >> 4) & 1) * 8 + (lid & 7);
    const int mc0 = m0 + ((lid >> 3) & 1) * 8;
    const uint32_t adrA0 = smb + SM_AT + krA * 256 + (((uint32_t)(mc0     ) * 2u) ^ xm);
    const uint32_t adrA1 = smb + SM_AT + krA * 256 + (((uint32_t)(mc0 + 16) * 2u) ^ xm);
    const int krB = ((lid >> 3) & 1) * 8 + (lid & 7);
    const int nc0 = n0 + ((lid >> 4) & 1) * 8;
    const uint32_t adrB0 = smb + SM_B + krB * 128 + (((uint32_t)(nc0     ) * 2u) ^ xm);
    const uint32_t adrB1 = smb + SM_B + krB * 128 + (((uint32_t)(nc0 + 16) * 2u) ^ xm);
    float* wsumf = (float*)(sm + SM_WSUM);

    for (int tile = bid; tile < NTILES; tile += NBLOCKS) {
        const int rr  = tile % TILES_PER_B;
        const int ph0 = (rr & 7) * 4;
        const int nh  = min(4, 31 - ph0);

        // ---- build At[k=(pos,cin)][m] from xs (A free: prev MMA long done) ----
        for (int it = 0; it < 16; ++it) {
            int idx = it * 256 + tid;
            int q = idx & 15, krow = idx >> 4;
            int pos = krow >> 5, cin = krow & 31;
            int dd = pos >> 2, dh = (pos >> 1) & 1, dw = pos & 1;
            int phl = q >> 2, pw0 = (q & 3) * 8;
            const char* srow = sm + SM_XS + ((cin * 2 + dd) * 5 + (phl + dh)) * 64;
            uint4 v;
            if (dw == 0) {
                v = *(const uint4*)(srow + pw0 * 2);
            } else {
                uint4 a = *(const uint4*)(srow + pw0 * 2);
                uint32_t bb = *(const uint32_t*)(srow + pw0 * 2 + 16);
                v.x = __funnelshift_r(a.x, a.y, 16);
                v.y = __funnelshift_r(a.y, a.z, 16);
                v.z = __funnelshift_r(a.z, a.w, 16);
                v.w = __funnelshift_r(a.w, bb, 16);
            }
            if (phl >= nh) v = make_uint4(0u, 0u, 0u, 0u);
            if (pw0 == 24) v.w &= 0x0000FFFFu;
            uint32_t off = (uint32_t)krow * 256u + (((uint32_t)q * 16u) ^ (((uint32_t)krow & 7u) << 4));
            *(uint4*)(sm + SM_AT + off) = v;
        }

        // ---- prefetch next tile's x slab (LDGs in flight during MMA) ----
        const int nxt = tile + NBLOCKS;
        const bool hn = nxt < NTILES;
        if (hn) {
            int nb = nxt / TILES_PER_B, nr = nxt % TILES_PER_B;
            ldg_slab(x, nb, nr >> 3, (nr & 7) * 4, tid, xr);
        }
        __syncthreads();             // A visible

        // ---- MMA e-loop ----
        float vmax[2][4][4];
        #pragma unroll
        for (int i = 0; i < 2; ++i)
        #pragma unroll
        for (int j = 0; j < 4; ++j)
        #pragma unroll
        for (int k = 0; k < 4; ++k) vmax[i][j][k] = -3.4e38f;

        #pragma unroll
        for (int e = 0; e < 8; ++e) {
            float acc[2][4][4];
            #pragma unroll
            for (int i = 0; i < 2; ++i)
            #pragma unroll
            for (int j = 0; j < 4; ++j)
            #pragma unroll
            for (int k = 0; k < 4; ++k) acc[i][j][k] = 0.f;

            #pragma unroll
            for (int pos = 0; pos < 8; ++pos) {
                if (pos & ~e & 7) continue;
                const int kd = (pos & 4) ? 0 : (((e >> 2) & 1) + 1);
                const int kh = (pos & 2) ? 0 : (((e >> 1) & 1) + 1);
                const int kw = (pos & 1) ? 0 : ((e & 1) + 1);
                const int t  = (kd * 3 + kh) * 3 + kw;
                #pragma unroll
                for (int kb2 = 0; kb2 < 2; ++kb2) {
                    const int kb = pos * 2 + kb2;
                    uint32_t A0[4], A1[4], B0[4], B1[4];
                    ldsm_x4t(A0, adrA0 + kb * 4096);
                    ldsm_x4t(A1, adrA1 + kb * 4096);
                    ldsm_x4t(B0, adrB0 + t * 4096 + kb2 * 2048);
                    ldsm_x4t(B1, adrB1 + t * 4096 + kb2 * 2048);
                    mma16816(acc[0][0], A0, B0[0], B0[1]);
                    mma16816(acc[0][1], A0, B0[2], B0[3]);
                    mma16816(acc[0][2], A0, B1[0], B1[1]);
                    mma16816(acc[0][3], A0, B1[2], B1[3]);
                    mma16816(acc[1][0], A1, B0[0], B0[1]);
                    mma16816(acc[1][1], A1, B0[2], B0[3]);
                    mma16816(acc[1][2], A1, B1[0], B1[1]);
                    mma16816(acc[1][3], A1, B1[2], B1[3]);
                }
            }
            #pragma unroll
            for (int i = 0; i < 2; ++i)
            #pragma unroll
            for (int j = 0; j < 4; ++j)
            #pragma unroll
            for (int k = 0; k < 4; ++k) vmax[i][j][k] = fmaxf(vmax[i][j][k], acc[i][j][k]);
        }

        // ---- epilogue: sum over windows -> per-cout partial ----
        #pragma unroll
        for (int nf = 0; nf < 4; ++nf) {
            float s0 = vmax[0][nf][0] + vmax[0][nf][2] + vmax[1][nf][0] + vmax[1][nf][2];
            float s1 = vmax[0][nf][1] + vmax[0][nf][3] + vmax[1][nf][1] + vmax[1][nf][3];
            #pragma unroll
            for (int off = 4; off < 32; off <<= 1) {
                s0 += __shfl_xor_sync(0xFFFFFFFFu, s0, off);
                s1 += __shfl_xor_sync(0xFFFFFFFFu, s1, off);
            }
            if (lid < 4) {
                wsumf[wid * 32 + nf * 8 + lid * 2]     = s0;
                wsumf[wid * 32 + nf * 8 + lid * 2 + 1] = s1;
            }
        }
        __syncthreads();
        if (tid < 64) {
            int ntc = tid >> 5, cl = tid & 31;
            float s = wsumf[(0 * 2 + ntc) * 32 + cl] + wsumf[(1 * 2 + ntc) * 32 + cl]
                    + wsumf[(2 * 2 + ntc) * 32 + cl] + wsumf[(3 * 2 + ntc) * 32 + cl];
            g_partials[tile * 64 + tid] = s;
        }
        __syncthreads();             // wsum consumed; all threads past A-build/MMA

        if (hn) sts_slab(sm, tid, xr);   // xs refill (consumes in-flight LDGs)
        __syncthreads();             // xs ready for next A-build
    }
}

__global__ void finalize_kernel(const float* __restrict__ bias, float* __restrict__ out)
{
    int bb = blockIdx.x;
    int t = threadIdx.x;
    int cout = t >> 2, q = t & 3;
    float s = 0.f;
    for (int i = q; i < TILES_PER_B; i += 4)
        s += g_partials[(bb * TILES_PER_B + i) * 64 + cout];
    s += __shfl_down_sync(0xFFFFFFFFu, s, 2, 4);
    s += __shfl_down_sync(0xFFFFFFFFu, s, 1, 4);
    if (q == 0) {
        float v = 0.5f * (s * (1.0f / 29791.0f) + bias[cout]);
        out[bb * 64 + cout] = fminf(fmaxf(v, 0.f), 1.f);
    }
}

extern "C" void kernel_launch(void* const* d_in, const int* in_sizes, int n_in,
                              void* d_out, int out_size)
{
    const float* x    = (const float*)d_in[0];
    const float* w    = (const float*)d_in[1];
    const float* bias = (const float*)d_in[2];
    float* out = (float*)d_out;

    cudaFuncSetAttribute(conv_mma_kernel,
                         cudaFuncAttributeMaxDynamicSharedMemorySize, SMEM_TOTAL);

    init_wb<<<216, 256>>>(w);
    conv_mma_kernel<<<NBLOCKS, 256, SMEM_TOTAL>>>(x);
    finalize_kernel<<<16, 256>>>(bias, out);
}